// round 1
// baseline (speedup 1.0000x reference)
#include <cuda_runtime.h>
#include <math.h>

#define BB   8
#define NN   4096
#define MM   4096
#define KK   64
#define TILE 128

#define FINF __int_as_float(0x7F800000)

// Scratch (no cudaMalloc allowed): per-(b,n) min over m, per-(b,m) min over n,
// plus squared norms. Stored as float; atomicMin done on int bits (valid: all
// values are >= 0, where IEEE float ordering == int ordering).
__device__ float g_min_m[BB * NN];  // min over m of sq-dist, indexed b*NN + n
__device__ float g_min_n[BB * MM];  // min over n of sq-dist, indexed b*MM + m
__device__ float g_x2[BB * NN];
__device__ float g_y2[BB * MM];

// ---------------------------------------------------------------------------
// Kernel 1: squared norms + init min arrays to +inf
// ---------------------------------------------------------------------------
__global__ void norms_init_kernel(const float* __restrict__ x,
                                  const float* __restrict__ y) {
    int i = blockIdx.x * blockDim.x + threadIdx.x;  // [0, 2*BB*NN)
    const int R = BB * NN;
    if (i < R) {
        const float4* p = (const float4*)(x + (size_t)i * KK);
        float s = 0.f;
#pragma unroll
        for (int j = 0; j < KK / 4; j++) {
            float4 v = p[j];
            s += v.x * v.x + v.y * v.y + v.z * v.z + v.w * v.w;
        }
        g_x2[i] = s;
        g_min_m[i] = FINF;
    } else {
        int r = i - R;
        const float4* p = (const float4*)(y + (size_t)r * KK);
        float s = 0.f;
#pragma unroll
        for (int j = 0; j < KK / 4; j++) {
            float4 v = p[j];
            s += v.x * v.x + v.y * v.y + v.z * v.z + v.w * v.w;
        }
        g_y2[r] = s;
        g_min_n[r] = FINF;
    }
}

// ---------------------------------------------------------------------------
// Kernel 2: 128x128 distance tile per block, 8x8 register blocking.
// sq(n,m) = x2[n] + y2[m] - 2*<x_n, y_m>; reduce tile to row/col mins.
// ---------------------------------------------------------------------------
extern __shared__ float s_mem[];

__global__ void __launch_bounds__(256, 2)
tile_kernel(const float* __restrict__ x, const float* __restrict__ y) {
    float* xs   = s_mem;                 // [KK][TILE] k-major  (64*128)
    float* ys   = s_mem + KK * TILE;     // [KK][TILE] k-major
    float* srow = ys + KK * TILE;        // [TILE] per-n tile min
    float* scol = srow + TILE;           // [TILE] per-m tile min

    const int b  = blockIdx.z;
    const int n0 = blockIdx.y * TILE;
    const int m0 = blockIdx.x * TILE;
    const int t  = threadIdx.x;

    if (t < TILE) { srow[t] = FINF; scol[t] = FINF; }

    // Load both tiles, transposing to k-major in shared.
    const float* xb = x + ((size_t)b * NN + n0) * KK;
    const float* yb = y + ((size_t)b * MM + m0) * KK;
#pragma unroll
    for (int pass = 0; pass < 8; pass++) {
        int idx = pass * 256 + t;        // 2048 float4 slots per tensor
        int row = idx & (TILE - 1);      // n (or m) within tile
        int k4  = idx >> 7;              // 0..15
        float4 v = *(const float4*)(xb + (size_t)row * KK + k4 * 4);
        xs[(k4 * 4 + 0) * TILE + row] = v.x;
        xs[(k4 * 4 + 1) * TILE + row] = v.y;
        xs[(k4 * 4 + 2) * TILE + row] = v.z;
        xs[(k4 * 4 + 3) * TILE + row] = v.w;
        float4 w = *(const float4*)(yb + (size_t)row * KK + k4 * 4);
        ys[(k4 * 4 + 0) * TILE + row] = w.x;
        ys[(k4 * 4 + 1) * TILE + row] = w.y;
        ys[(k4 * 4 + 2) * TILE + row] = w.z;
        ys[(k4 * 4 + 3) * TILE + row] = w.w;
    }
    __syncthreads();

    const int tx = t & 15;   // m direction
    const int ty = t >> 4;   // n direction

    float acc[8][8];
#pragma unroll
    for (int i = 0; i < 8; i++)
#pragma unroll
        for (int j = 0; j < 8; j++) acc[i][j] = 0.f;

#pragma unroll 4
    for (int k = 0; k < KK; k++) {
        float4 a0 = *(const float4*)&xs[k * TILE + ty * 4];
        float4 a1 = *(const float4*)&xs[k * TILE + ty * 4 + 64];
        float4 b0 = *(const float4*)&ys[k * TILE + tx * 4];
        float4 b1 = *(const float4*)&ys[k * TILE + tx * 4 + 64];
        float a[8] = {a0.x, a0.y, a0.z, a0.w, a1.x, a1.y, a1.z, a1.w};
        float c[8] = {b0.x, b0.y, b0.z, b0.w, b1.x, b1.y, b1.z, b1.w};
#pragma unroll
        for (int i = 0; i < 8; i++)
#pragma unroll
            for (int j = 0; j < 8; j++) acc[i][j] = fmaf(a[i], c[j], acc[i][j]);
    }

    // Epilogue: squared distances + local row/col mins.
    float x2r[8], y2r[8];
#pragma unroll
    for (int i = 0; i < 8; i++) {
        int ni = ty * 4 + (i < 4 ? i : 60 + i);   // 60+i == 64 + (i-4)
        int mi = tx * 4 + (i < 4 ? i : 60 + i);
        x2r[i] = g_x2[b * NN + n0 + ni];
        y2r[i] = g_y2[b * MM + m0 + mi];
    }

    float rmin[8], cmin[8];
#pragma unroll
    for (int i = 0; i < 8; i++) { rmin[i] = FINF; cmin[i] = FINF; }
#pragma unroll
    for (int i = 0; i < 8; i++) {
#pragma unroll
        for (int j = 0; j < 8; j++) {
            float sq = fmaxf(x2r[i] + y2r[j] - 2.f * acc[i][j], 0.f);
            rmin[i] = fminf(rmin[i], sq);
            cmin[j] = fminf(cmin[j], sq);
        }
    }

#pragma unroll
    for (int i = 0; i < 8; i++) {
        int ni = ty * 4 + (i < 4 ? i : 60 + i);
        int mi = tx * 4 + (i < 4 ? i : 60 + i);
        atomicMin((int*)&srow[ni], __float_as_int(rmin[i]));
        atomicMin((int*)&scol[mi], __float_as_int(cmin[i]));
    }
    __syncthreads();

    if (t < TILE) {
        atomicMin((int*)&g_min_m[b * NN + n0 + t], __float_as_int(srow[t]));
    } else {
        int j = t - TILE;
        atomicMin((int*)&g_min_n[b * MM + m0 + j], __float_as_int(scol[j]));
    }
}

// ---------------------------------------------------------------------------
// Kernel 3: final reduction: loss = sum(sqrt(mins)) / (B * 4096)
// ---------------------------------------------------------------------------
__global__ void reduce_kernel(float* __restrict__ out) {
    __shared__ float ssum[256];
    int t = threadIdx.x;
    float s = 0.f;
    for (int i = t; i < BB * NN; i += 256)
        s += sqrtf(g_min_m[i]) + sqrtf(g_min_n[i]);
    ssum[t] = s;
    __syncthreads();
#pragma unroll
    for (int off = 128; off > 0; off >>= 1) {
        if (t < off) ssum[t] += ssum[t + off];
        __syncthreads();
    }
    if (t == 0) out[0] = ssum[0] * (1.0f / (BB * NN));
}

// ---------------------------------------------------------------------------
extern "C" void kernel_launch(void* const* d_in, const int* in_sizes, int n_in,
                              void* d_out, int out_size) {
    const float* x = (const float*)d_in[0];   // input1 [B, N, K]
    const float* y = (const float*)d_in[1];   // input2 [B, M, K]
    float* out = (float*)d_out;

    const size_t SMEM = (2 * KK * TILE + 2 * TILE) * sizeof(float);  // 66560 B
    cudaFuncSetAttribute(tile_kernel,
                         cudaFuncAttributeMaxDynamicSharedMemorySize, (int)SMEM);

    norms_init_kernel<<<(2 * BB * NN) / 256, 256>>>(x, y);

    dim3 grid(MM / TILE, NN / TILE, BB);
    tile_kernel<<<grid, 256, SMEM>>>(x, y);

    reduce_kernel<<<1, 256>>>(out);
}

// round 3
// speedup vs baseline: 1.8993x; 1.8993x over previous
#include <cuda_runtime.h>
#include <cuda_bf16.h>
#include <math.h>
#include <stdint.h>

#define BB   8
#define NN   4096
#define MM   4096
#define KK   64

#define FINF __int_as_float(0x7F800000)

__device__ float g_min_m[BB * NN];   // min over m of sq-dist  (b*NN + n)
__device__ float g_min_n[BB * MM];   // min over n of sq-dist  (b*MM + m)
__device__ float g_x2[BB * NN];
__device__ float g_y2[BB * MM];

__device__ __forceinline__ uint32_t s2u(const void* p) {
    uint32_t a;
    asm("{ .reg .u64 t; cvta.to.shared.u64 t, %1; cvt.u32.u64 %0, t; }"
        : "=r"(a) : "l"(p));
    return a;
}

#define SWZ(o) ((o) ^ (((o) >> 3) & 0x70))

// SMEM byte offsets
#define SM_AHI  0
#define SM_ALO  16384
#define SM_BHI  32768
#define SM_BLO  49152
#define SM_X2   65536
#define SM_Y2   66048
#define SM_ROW  66560
#define SM_COL  67072
#define SMEM_SZ 67584

// ---------------------------------------------------------------------------
// Kernel 1: squared norms + init min arrays to +inf
// ---------------------------------------------------------------------------
__global__ void norms_init_kernel(const float* __restrict__ x,
                                  const float* __restrict__ y) {
    int i = blockIdx.x * blockDim.x + threadIdx.x;
    const int R = BB * NN;
    const float* src = (i < R) ? (x + (size_t)i * KK) : (y + (size_t)(i - R) * KK);
    float s = 0.f;
#pragma unroll
    for (int j = 0; j < KK / 4; j++) {
        float4 v = ((const float4*)src)[j];
        s += v.x * v.x + v.y * v.y + v.z * v.z + v.w * v.w;
    }
    if (i < R) { g_x2[i] = s; g_min_m[i] = FINF; }
    else       { g_y2[i - R] = s; g_min_n[i - R] = FINF; }
}

// fp32 -> (bf16 hi, bf16 lo) split of a float4
__device__ __forceinline__ void cvt_split(float4 v, uint2& h, uint2& l) {
    __nv_bfloat162 h01 = __floats2bfloat162_rn(v.x, v.y);
    __nv_bfloat162 h23 = __floats2bfloat162_rn(v.z, v.w);
    float r0 = v.x - __low2float(h01);
    float r1 = v.y - __high2float(h01);
    float r2 = v.z - __low2float(h23);
    float r3 = v.w - __high2float(h23);
    __nv_bfloat162 l01 = __floats2bfloat162_rn(r0, r1);
    __nv_bfloat162 l23 = __floats2bfloat162_rn(r2, r3);
    h.x = *reinterpret_cast<uint32_t*>(&h01);
    h.y = *reinterpret_cast<uint32_t*>(&h23);
    l.x = *reinterpret_cast<uint32_t*>(&l01);
    l.y = *reinterpret_cast<uint32_t*>(&l23);
}

__device__ __forceinline__ void mma16816(float* c, const uint32_t* a,
                                         const uint32_t* b) {
    asm volatile(
        "mma.sync.aligned.m16n8k16.row.col.f32.bf16.bf16.f32 "
        "{%0,%1,%2,%3}, {%4,%5,%6,%7}, {%8,%9}, {%0,%1,%2,%3};"
        : "+f"(c[0]), "+f"(c[1]), "+f"(c[2]), "+f"(c[3])
        : "r"(a[0]), "r"(a[1]), "r"(a[2]), "r"(a[3]), "r"(b[0]), "r"(b[1]));
}

// ---------------------------------------------------------------------------
// Kernel 2: 128x128 tile per CTA, warp-level bf16-split HMMA (virtual K=192)
// ---------------------------------------------------------------------------
extern __shared__ char smem[];

__global__ void __launch_bounds__(256, 2)
tile_hmma_kernel(const float* __restrict__ x, const float* __restrict__ y) {
    const uint32_t sb = s2u(smem);
    const int t = threadIdx.x, lane = t & 31, w = t >> 5;
    const int wr = w >> 2;            // 0..1  : 64-row (n) band
    const int wc = w & 3;             // 0..3  : 32-col (m) band
    const int b = blockIdx.z, n0 = blockIdx.y * 128, m0 = blockIdx.x * 128;

    float* sx2  = (float*)(smem + SM_X2);
    float* sy2  = (float*)(smem + SM_Y2);
    float* srow = (float*)(smem + SM_ROW);
    float* scol = (float*)(smem + SM_COL);

    if (t < 128) { sx2[t] = g_x2[b * NN + n0 + t]; srow[t] = FINF; }
    else { sy2[t - 128] = g_y2[b * MM + m0 + t - 128]; scol[t - 128] = FINF; }

    // Load + split-convert A (x, 128x64) and B (y, 128x64) into SW128 smem.
    const float* xb = x + ((size_t)b * NN + n0) * KK;
    const float* yb = y + ((size_t)b * MM + m0) * KK;
#pragma unroll
    for (int p = 0; p < 8; p++) {
        int idx = p * 256 + t;
        int row = idx >> 4, k4 = idx & 15;
        float4 v = *(const float4*)(xb + row * KK + k4 * 4);
        uint2 h, l; cvt_split(v, h, l);
        uint32_t sw = SWZ((uint32_t)(row * 128 + k4 * 8));
        *(uint2*)(smem + SM_AHI + sw) = h;
        *(uint2*)(smem + SM_ALO + sw) = l;
    }
#pragma unroll
    for (int p = 0; p < 8; p++) {
        int idx = p * 256 + t;
        int row = idx >> 4, k4 = idx & 15;
        float4 v = *(const float4*)(yb + row * KK + k4 * 4);
        uint2 h, l; cvt_split(v, h, l);
        uint32_t sw = SWZ((uint32_t)(row * 128 + k4 * 8));
        *(uint2*)(smem + SM_BHI + sw) = h;
        *(uint2*)(smem + SM_BLO + sw) = l;
    }
    __syncthreads();

    // Per-lane ldmatrix base offsets (bytes, pre-swizzle).
    const int tq = lane >> 3, tr = lane & 7;
    uint32_t aOff[4], bOff[4];
#pragma unroll
    for (int mt = 0; mt < 4; mt++)
        aOff[mt] = (uint32_t)((wr * 64 + mt * 16 + (tq & 1) * 8 + tr) * 128 +
                              (tq >> 1) * 16);
    const int l16 = lane & 15;
#pragma unroll
    for (int nt = 0; nt < 4; nt++)
        bOff[nt] = (uint32_t)((wc * 32 + nt * 8 + (l16 & 7)) * 128 +
                              (l16 >> 3) * 16);

    float acc[4][4][4];
#pragma unroll
    for (int i = 0; i < 4; i++)
#pragma unroll
        for (int j = 0; j < 4; j++)
#pragma unroll
            for (int e = 0; e < 4; e++) acc[i][j][e] = 0.f;

    // Virtual K=192: phase 0: Ahi*Bhi, phase 1: Alo*Bhi, phase 2: Ahi*Blo.
#pragma unroll
    for (int ks = 0; ks < 12; ks++) {
        const int ph = ks >> 2, kk = ks & 3;
        const uint32_t abase = sb + ((ph == 1) ? SM_ALO : SM_AHI);
        const uint32_t bbase = sb + ((ph == 2) ? SM_BLO : SM_BHI);
        const uint32_t kcol = kk * 32;

        uint32_t a[4][4], bf[4][2];
#pragma unroll
        for (int mt = 0; mt < 4; mt++) {
            uint32_t addr = abase + SWZ(aOff[mt] + kcol);
            asm volatile("ldmatrix.sync.aligned.m8n8.x4.shared.b16 "
                         "{%0,%1,%2,%3}, [%4];"
                         : "=r"(a[mt][0]), "=r"(a[mt][1]),
                           "=r"(a[mt][2]), "=r"(a[mt][3]) : "r"(addr));
        }
#pragma unroll
        for (int nt = 0; nt < 4; nt++) {
            uint32_t addr = bbase + SWZ(bOff[nt] + kcol);
            asm volatile("ldmatrix.sync.aligned.m8n8.x2.shared.b16 "
                         "{%0,%1}, [%2];"
                         : "=r"(bf[nt][0]), "=r"(bf[nt][1]) : "r"(addr));
        }
#pragma unroll
        for (int mt = 0; mt < 4; mt++)
#pragma unroll
            for (int nt = 0; nt < 4; nt++)
                mma16816(acc[mt][nt], a[mt], bf[nt]);
    }

    // Epilogue: fragment layout m16n8: elem e -> row l/4 + (e>>1)*8,
    //                                    col 2*(l%4) + (e&1)
    float x2r[8], y2c[8];
#pragma unroll
    for (int mt = 0; mt < 4; mt++)
#pragma unroll
        for (int s = 0; s < 2; s++)
            x2r[mt * 2 + s] = sx2[wr * 64 + mt * 16 + (lane >> 2) + s * 8];
#pragma unroll
    for (int nt = 0; nt < 4; nt++)
#pragma unroll
        for (int e = 0; e < 2; e++)
            y2c[nt * 2 + e] = sy2[wc * 32 + nt * 8 + 2 * (lane & 3) + e];

    float rowmin[8], colmin[8];
#pragma unroll
    for (int i = 0; i < 8; i++) { rowmin[i] = FINF; colmin[i] = FINF; }

#pragma unroll
    for (int mt = 0; mt < 4; mt++)
#pragma unroll
        for (int nt = 0; nt < 4; nt++)
#pragma unroll
            for (int e = 0; e < 4; e++) {
                const int ri = mt * 2 + (e >> 1), cj = nt * 2 + (e & 1);
                float v = -2.f * acc[mt][nt][e];
                rowmin[ri] = fminf(rowmin[ri], v + y2c[cj]);
                colmin[cj] = fminf(colmin[cj], v + x2r[ri]);
            }

    // Row mins: reduce over lanes sharing a row (same l/4 -> xor 1,2).
#pragma unroll
    for (int off = 1; off <= 2; off <<= 1)
#pragma unroll
        for (int i = 0; i < 8; i++)
            rowmin[i] = fminf(rowmin[i], __shfl_xor_sync(~0u, rowmin[i], off));
    if ((lane & 3) == 0) {
#pragma unroll
        for (int mt = 0; mt < 4; mt++)
#pragma unroll
            for (int s = 0; s < 2; s++) {
                int row = wr * 64 + mt * 16 + (lane >> 2) + s * 8;
                float v = fmaxf(rowmin[mt * 2 + s] + x2r[mt * 2 + s], 0.f);
                atomicMin((int*)&srow[row], __float_as_int(v));
            }
    }

    // Col mins: reduce over lanes sharing a col (same l%4 -> xor 4,8,16).
#pragma unroll
    for (int off = 4; off <= 16; off <<= 1)
#pragma unroll
        for (int i = 0; i < 8; i++)
            colmin[i] = fminf(colmin[i], __shfl_xor_sync(~0u, colmin[i], off));
    if (lane < 4) {
#pragma unroll
        for (int nt = 0; nt < 4; nt++)
#pragma unroll
            for (int e = 0; e < 2; e++) {
                int col = wc * 32 + nt * 8 + 2 * lane + e;
                float v = fmaxf(colmin[nt * 2 + e] + y2c[nt * 2 + e], 0.f);
                atomicMin((int*)&scol[col], __float_as_int(v));
            }
    }

    __syncthreads();
    if (t < 128)
        atomicMin((int*)&g_min_m[b * NN + n0 + t], __float_as_int(srow[t]));
    else
        atomicMin((int*)&g_min_n[b * MM + m0 + t - 128],
                  __float_as_int(scol[t - 128]));
}

// ---------------------------------------------------------------------------
// Kernel 3: loss = sum(sqrt(mins)) / (B * 4096)
// ---------------------------------------------------------------------------
__global__ void reduce_kernel(float* __restrict__ out) {
    __shared__ float ssum[256];
    int t = threadIdx.x;
    float s = 0.f;
    for (int i = t; i < BB * NN; i += 256)
        s += sqrtf(g_min_m[i]) + sqrtf(g_min_n[i]);
    ssum[t] = s;
    __syncthreads();
#pragma unroll
    for (int off = 128; off > 0; off >>= 1) {
        if (t < off) ssum[t] += ssum[t + off];
        __syncthreads();
    }
    if (t == 0) out[0] = ssum[0] * (1.0f / (BB * NN));
}

// ---------------------------------------------------------------------------
extern "C" void kernel_launch(void* const* d_in, const int* in_sizes, int n_in,
                              void* d_out, int out_size) {
    const float* x = (const float*)d_in[0];   // input1 [B, N, K]
    const float* y = (const float*)d_in[1];   // input2 [B, M, K]
    float* out = (float*)d_out;

    cudaFuncSetAttribute(tile_hmma_kernel,
                         cudaFuncAttributeMaxDynamicSharedMemorySize, SMEM_SZ);

    norms_init_kernel<<<(2 * BB * NN) / 256, 256>>>(x, y);

    dim3 grid(MM / 128, NN / 128, BB);
    tile_hmma_kernel<<<grid, 256, SMEM_SZ>>>(x, y);

    reduce_kernel<<<1, 256>>>(out);
}

// round 5
// speedup vs baseline: 3.6640x; 1.9291x over previous
#include <cuda_runtime.h>
#include <cuda_bf16.h>
#include <math.h>
#include <stdint.h>

#define BB   8
#define NN   4096
#define MM   4096
#define KK   64

#define FINF __int_as_float(0x7F800000)

__device__ float g_min_m[BB * NN];   // min over m of sq-dist  (b*NN + n)
__device__ float g_min_n[BB * MM];   // min over n of sq-dist  (b*MM + m)
__device__ float g_x2[BB * NN];
__device__ float g_y2[BB * MM];

__device__ __forceinline__ uint32_t s2u(const void* p) {
    uint32_t a;
    asm("{ .reg .u64 t; cvta.to.shared.u64 t, %1; cvt.u32.u64 %0, t; }"
        : "=r"(a) : "l"(p));
    return a;
}

#define SWZ(o) ((o) ^ (((o) >> 3) & 0x70))

// SMEM byte offsets
#define SM_A    0              // x tile, bf16, 128x64 K-major (16 KB)
#define SM_BHI  16384          // y hi tile (16 KB)
#define SM_BLO  32768          // y lo tile (16 KB)
#define SM_X2   49152
#define SM_Y2   49664
#define SM_ROW  50176
#define SM_COL  50688
#define SMEM_SZ 51200

// ---------------------------------------------------------------------------
// Kernel 1: squared norms + init min arrays. 4 lanes per row.
// ---------------------------------------------------------------------------
__global__ void norms_init_kernel(const float* __restrict__ x,
                                  const float* __restrict__ y) {
    int gid = blockIdx.x * blockDim.x + threadIdx.x;   // [0, 8*BB*NN)
    int i   = gid >> 2;                                // row
    int sl  = gid & 3;                                 // 4-lane slice
    const int R = BB * NN;
    const float* src = (i < R) ? (x + (size_t)i * KK) : (y + (size_t)(i - R) * KK);
    float s = 0.f;
#pragma unroll
    for (int j = 0; j < 4; j++) {
        float4 v = ((const float4*)src)[sl * 4 + j];
        s += v.x * v.x + v.y * v.y + v.z * v.z + v.w * v.w;
    }
    s += __shfl_xor_sync(~0u, s, 1);
    s += __shfl_xor_sync(~0u, s, 2);
    if (sl == 0) {
        if (i < R) { g_x2[i] = s; g_min_m[i] = FINF; }
        else       { g_y2[i - R] = s; g_min_n[i - R] = FINF; }
    }
}

// fp32 float4 -> bf16x4 (plain round)
__device__ __forceinline__ uint2 cvt_rn4(float4 v) {
    __nv_bfloat162 p01 = __floats2bfloat162_rn(v.x, v.y);
    __nv_bfloat162 p23 = __floats2bfloat162_rn(v.z, v.w);
    uint2 r;
    r.x = *reinterpret_cast<uint32_t*>(&p01);
    r.y = *reinterpret_cast<uint32_t*>(&p23);
    return r;
}

// fp32 float4 -> (bf16 hi, bf16 lo)
__device__ __forceinline__ void cvt_split(float4 v, uint2& h, uint2& l) {
    __nv_bfloat162 h01 = __floats2bfloat162_rn(v.x, v.y);
    __nv_bfloat162 h23 = __floats2bfloat162_rn(v.z, v.w);
    float r0 = v.x - __low2float(h01);
    float r1 = v.y - __high2float(h01);
    float r2 = v.z - __low2float(h23);
    float r3 = v.w - __high2float(h23);
    __nv_bfloat162 l01 = __floats2bfloat162_rn(r0, r1);
    __nv_bfloat162 l23 = __floats2bfloat162_rn(r2, r3);
    h.x = *reinterpret_cast<uint32_t*>(&h01);
    h.y = *reinterpret_cast<uint32_t*>(&h23);
    l.x = *reinterpret_cast<uint32_t*>(&l01);
    l.y = *reinterpret_cast<uint32_t*>(&l23);
}

__device__ __forceinline__ void mma16816(float* c, const uint32_t* a,
                                         const uint32_t* b) {
    asm volatile(
        "mma.sync.aligned.m16n8k16.row.col.f32.bf16.bf16.f32 "
        "{%0,%1,%2,%3}, {%4,%5,%6,%7}, {%8,%9}, {%0,%1,%2,%3};"
        : "+f"(c[0]), "+f"(c[1]), "+f"(c[2]), "+f"(c[3])
        : "r"(a[0]), "r"(a[1]), "r"(a[2]), "r"(a[3]), "r"(b[0]), "r"(b[1]));
}

// ---------------------------------------------------------------------------
// Kernel 2: 128x128 tile per CTA; x_bf * (y_hi + y_lo), virtual K=128.
// ---------------------------------------------------------------------------
extern __shared__ char smem[];

__global__ void __launch_bounds__(256, 2)
tile_hmma_kernel(const float* __restrict__ x, const float* __restrict__ y) {
    const uint32_t sb = s2u(smem);
    const int t = threadIdx.x, lane = t & 31, w = t >> 5;
    const int wr = w >> 2;            // 0..1  : 64-row (n) band
    const int wc = w & 3;             // 0..3  : 32-col (m) band
    const int b = blockIdx.z, n0 = blockIdx.y * 128, m0 = blockIdx.x * 128;

    float* sx2  = (float*)(smem + SM_X2);
    float* sy2  = (float*)(smem + SM_Y2);
    float* srow = (float*)(smem + SM_ROW);
    float* scol = (float*)(smem + SM_COL);

    if (t < 128) { sx2[t] = g_x2[b * NN + n0 + t]; srow[t] = FINF; }
    else { sy2[t - 128] = g_y2[b * MM + m0 + t - 128]; scol[t - 128] = FINF; }

    // Load + convert A (x, plain bf16) and B (y, hi/lo split), SW128 K-major.
    const float* xb = x + ((size_t)b * NN + n0) * KK;
    const float* yb = y + ((size_t)b * MM + m0) * KK;
#pragma unroll
    for (int p = 0; p < 8; p++) {
        int idx = p * 256 + t;
        int row = idx >> 4, k4 = idx & 15;
        uint32_t sw = SWZ((uint32_t)(row * 128 + k4 * 8));
        float4 v = *(const float4*)(xb + row * KK + k4 * 4);
        *(uint2*)(smem + SM_A + sw) = cvt_rn4(v);
        float4 u = *(const float4*)(yb + row * KK + k4 * 4);
        uint2 h, l; cvt_split(u, h, l);
        *(uint2*)(smem + SM_BHI + sw) = h;
        *(uint2*)(smem + SM_BLO + sw) = l;
    }
    __syncthreads();

    // Per-lane ldmatrix base offsets (bytes, pre-swizzle).
    const int tq = lane >> 3, tr = lane & 7;
    uint32_t aOff[4], bOff[4];
#pragma unroll
    for (int mt = 0; mt < 4; mt++)
        aOff[mt] = (uint32_t)((wr * 64 + mt * 16 + (tq & 1) * 8 + tr) * 128 +
                              (tq >> 1) * 16);
    const int l16 = lane & 15;
#pragma unroll
    for (int nt = 0; nt < 4; nt++)
        bOff[nt] = (uint32_t)((wc * 32 + nt * 8 + (l16 & 7)) * 128 +
                              (l16 >> 3) * 16);

    float acc[4][4][4];
#pragma unroll
    for (int i = 0; i < 4; i++)
#pragma unroll
        for (int j = 0; j < 4; j++)
#pragma unroll
            for (int e = 0; e < 4; e++) acc[i][j][e] = 0.f;

    // K loop: per k16 block load A once, run B_hi then B_lo phases.
#pragma unroll
    for (int kk = 0; kk < 4; kk++) {
        const uint32_t kcol = kk * 32;

        uint32_t a[4][4];
#pragma unroll
        for (int mt = 0; mt < 4; mt++) {
            uint32_t addr = sb + SM_A + SWZ(aOff[mt] + kcol);
            asm volatile("ldmatrix.sync.aligned.m8n8.x4.shared.b16 "
                         "{%0,%1,%2,%3}, [%4];"
                         : "=r"(a[mt][0]), "=r"(a[mt][1]),
                           "=r"(a[mt][2]), "=r"(a[mt][3]) : "r"(addr));
        }
#pragma unroll
        for (int ph = 0; ph < 2; ph++) {
            const uint32_t bbase = sb + (ph ? SM_BLO : SM_BHI);
            uint32_t bf[4][2];
#pragma unroll
            for (int nt = 0; nt < 4; nt++) {
                uint32_t addr = bbase + SWZ(bOff[nt] + kcol);
                asm volatile("ldmatrix.sync.aligned.m8n8.x2.shared.b16 "
                             "{%0,%1}, [%2];"
                             : "=r"(bf[nt][0]), "=r"(bf[nt][1]) : "r"(addr));
            }
#pragma unroll
            for (int mt = 0; mt < 4; mt++)
#pragma unroll
                for (int nt = 0; nt < 4; nt++)
                    mma16816(acc[mt][nt], a[mt], bf[nt]);
        }
    }

    // Epilogue: fragment (m16n8): elem e -> row l/4 + (e>>1)*8, col 2*(l%4)+(e&1)
    float x2r[8], y2c[8];
#pragma unroll
    for (int mt = 0; mt < 4; mt++)
#pragma unroll
        for (int s = 0; s < 2; s++)
            x2r[mt * 2 + s] = sx2[wr * 64 + mt * 16 + (lane >> 2) + s * 8];
#pragma unroll
    for (int nt = 0; nt < 4; nt++)
#pragma unroll
        for (int e = 0; e < 2; e++)
            y2c[nt * 2 + e] = sy2[wc * 32 + nt * 8 + 2 * (lane & 3) + e];

    float rowmin[8], colmin[8];
#pragma unroll
    for (int i = 0; i < 8; i++) { rowmin[i] = FINF; colmin[i] = FINF; }

#pragma unroll
    for (int mt = 0; mt < 4; mt++)
#pragma unroll
        for (int nt = 0; nt < 4; nt++)
#pragma unroll
            for (int e = 0; e < 4; e++) {
                const int ri = mt * 2 + (e >> 1), cj = nt * 2 + (e & 1);
                float v = -2.f * acc[mt][nt][e];
                rowmin[ri] = fminf(rowmin[ri], v + y2c[cj]);
                colmin[cj] = fminf(colmin[cj], v + x2r[ri]);
            }

    // Row mins: reduce over lanes sharing a row (xor 1,2).
#pragma unroll
    for (int off = 1; off <= 2; off <<= 1)
#pragma unroll
        for (int i = 0; i < 8; i++)
            rowmin[i] = fminf(rowmin[i], __shfl_xor_sync(~0u, rowmin[i], off));
    if ((lane & 3) == 0) {
#pragma unroll
        for (int mt = 0; mt < 4; mt++)
#pragma unroll
            for (int s = 0; s < 2; s++) {
                int row = wr * 64 + mt * 16 + (lane >> 2) + s * 8;
                float v = fmaxf(rowmin[mt * 2 + s] + x2r[mt * 2 + s], 0.f);
                atomicMin((int*)&srow[row], __float_as_int(v));
            }
    }

    // Col mins: reduce over lanes sharing a col (xor 4,8,16).
#pragma unroll
    for (int off = 4; off <= 16; off <<= 1)
#pragma unroll
        for (int i = 0; i < 8; i++)
            colmin[i] = fminf(colmin[i], __shfl_xor_sync(~0u, colmin[i], off));
    if (lane < 4) {
#pragma unroll
        for (int nt = 0; nt < 4; nt++)
#pragma unroll
            for (int e = 0; e < 2; e++) {
                int col = wc * 32 + nt * 8 + 2 * lane + e;
                float v = fmaxf(colmin[nt * 2 + e] + y2c[nt * 2 + e], 0.f);
                atomicMin((int*)&scol[col], __float_as_int(v));
            }
    }

    __syncthreads();
    if (t < 128)
        atomicMin((int*)&g_min_m[b * NN + n0 + t], __float_as_int(srow[t]));
    else
        atomicMin((int*)&g_min_n[b * MM + m0 + t - 128],
                  __float_as_int(scol[t - 128]));
}

// ---------------------------------------------------------------------------
// Kernel 3: loss = sum(sqrt(mins)) / (B * 4096)
// ---------------------------------------------------------------------------
__global__ void reduce_kernel(float* __restrict__ out) {
    __shared__ float ssum[1024];
    int t = threadIdx.x;
    float s = 0.f;
    for (int i = t; i < BB * NN; i += 1024)
        s += sqrtf(g_min_m[i]) + sqrtf(g_min_n[i]);
    ssum[t] = s;
    __syncthreads();
#pragma unroll
    for (int off = 512; off > 0; off >>= 1) {
        if (t < off) ssum[t] += ssum[t + off];
        __syncthreads();
    }
    if (t == 0) out[0] = ssum[0] * (1.0f / (BB * NN));
}

// ---------------------------------------------------------------------------
extern "C" void kernel_launch(void* const* d_in, const int* in_sizes, int n_in,
                              void* d_out, int out_size) {
    const float* x = (const float*)d_in[0];   // input1 [B, N, K]
    const float* y = (const float*)d_in[1];   // input2 [B, M, K]
    float* out = (float*)d_out;

    cudaFuncSetAttribute(tile_hmma_kernel,
                         cudaFuncAttributeMaxDynamicSharedMemorySize, SMEM_SZ);

    norms_init_kernel<<<(8 * BB * NN) / 256, 256>>>(x, y);

    dim3 grid(MM / 128, NN / 128, BB);
    tile_hmma_kernel<<<grid, 256, SMEM_SZ>>>(x, y);

    reduce_kernel<<<1, 1024>>>(out);
}

// round 6
// speedup vs baseline: 4.2633x; 1.1636x over previous
#include <cuda_runtime.h>
#include <cuda_bf16.h>
#include <math.h>
#include <stdint.h>

#define BB   8
#define NN   4096
#define MM   4096
#define KK   64

#define FINF __int_as_float(0x7F800000)

__device__ float g_min_m[BB * NN];   // min over m of sq-dist  (b*NN + n)
__device__ float g_min_n[BB * MM];   // min over n of sq-dist  (b*MM + m)
__device__ float g_x2[BB * NN];
__device__ float g_y2[BB * MM];

// Pre-converted, pre-swizzled 16 KB tile images (smem-ready).
__device__ unsigned char g_xbf[BB * NN * 128];     // 4 MB, bf16 x
__device__ unsigned char g_yhi[BB * MM * 128];     // 4 MB, bf16 hi(y)
__device__ unsigned char g_ylo[BB * MM * 128];     // 4 MB, bf16 lo(y)

__device__ __forceinline__ uint32_t s2u(const void* p) {
    uint32_t a;
    asm("{ .reg .u64 t; cvta.to.shared.u64 t, %1; cvt.u32.u64 %0, t; }"
        : "=r"(a) : "l"(p));
    return a;
}

#define SWZ(o) ((o) ^ (((o) >> 3) & 0x70))

// SMEM byte offsets
#define SM_A    0              // x tile image (16 KB)
#define SM_BHI  16384          // y hi tile image (16 KB)
#define SM_BLO  32768          // y lo tile image (16 KB)
#define SM_X2   49152
#define SM_Y2   49664
#define SM_ROW  50176
#define SM_COL  50688
#define SMEM_SZ 51200

// ---------------------------------------------------------------------------
// Kernel 1: convert + swizzle-pack + norms + min-init. 16 lanes per row.
// gid = row*16 + k4.
// ---------------------------------------------------------------------------
__global__ void prep_kernel(const float* __restrict__ x,
                            const float* __restrict__ y) {
    const int gid = blockIdx.x * blockDim.x + threadIdx.x;
    const int row = gid >> 4, k4 = gid & 15;
    const int R = BB * NN;
    const bool isx = row < R;
    const int r = isx ? row : row - R;

    const float4 v = ((const float4*)((isx ? x : y) + (size_t)r * KK))[k4];

    // tile image offset: tile = r/128 (b*32 + blk), row-in-tile = r%128
    const uint32_t off = (uint32_t)(r >> 7) * 16384u +
                         SWZ((uint32_t)((r & 127) * 128 + k4 * 8));

    if (isx) {
        __nv_bfloat162 p01 = __floats2bfloat162_rn(v.x, v.y);
        __nv_bfloat162 p23 = __floats2bfloat162_rn(v.z, v.w);
        uint2 h;
        h.x = *reinterpret_cast<uint32_t*>(&p01);
        h.y = *reinterpret_cast<uint32_t*>(&p23);
        *(uint2*)(g_xbf + off) = h;
    } else {
        __nv_bfloat162 h01 = __floats2bfloat162_rn(v.x, v.y);
        __nv_bfloat162 h23 = __floats2bfloat162_rn(v.z, v.w);
        float r0 = v.x - __low2float(h01);
        float r1 = v.y - __high2float(h01);
        float r2 = v.z - __low2float(h23);
        float r3 = v.w - __high2float(h23);
        __nv_bfloat162 l01 = __floats2bfloat162_rn(r0, r1);
        __nv_bfloat162 l23 = __floats2bfloat162_rn(r2, r3);
        uint2 h, l;
        h.x = *reinterpret_cast<uint32_t*>(&h01);
        h.y = *reinterpret_cast<uint32_t*>(&h23);
        l.x = *reinterpret_cast<uint32_t*>(&l01);
        l.y = *reinterpret_cast<uint32_t*>(&l23);
        *(uint2*)(g_yhi + off) = h;
        *(uint2*)(g_ylo + off) = l;
    }

    // Row norm: reduce over the 16 lanes of this row.
    float s = v.x * v.x + v.y * v.y + v.z * v.z + v.w * v.w;
    s += __shfl_xor_sync(~0u, s, 1);
    s += __shfl_xor_sync(~0u, s, 2);
    s += __shfl_xor_sync(~0u, s, 4);
    s += __shfl_xor_sync(~0u, s, 8);
    if (k4 == 0) {
        if (isx) { g_x2[r] = s; g_min_m[r] = FINF; }
        else     { g_y2[r] = s; g_min_n[r] = FINF; }
    }
}

__device__ __forceinline__ void mma16816(float* c, const uint32_t* a,
                                         const uint32_t* b) {
    asm volatile(
        "mma.sync.aligned.m16n8k16.row.col.f32.bf16.bf16.f32 "
        "{%0,%1,%2,%3}, {%4,%5,%6,%7}, {%8,%9}, {%0,%1,%2,%3};"
        : "+f"(c[0]), "+f"(c[1]), "+f"(c[2]), "+f"(c[3])
        : "r"(a[0]), "r"(a[1]), "r"(a[2]), "r"(a[3]), "r"(b[0]), "r"(b[1]));
}

__device__ __forceinline__ void cp16(uint32_t dst, const void* src) {
    asm volatile("cp.async.cg.shared.global [%0], [%1], 16;"
                 :: "r"(dst), "l"(src) : "memory");
}

// ---------------------------------------------------------------------------
// Kernel 2: 128x128 tile per CTA; cp.async pre-swizzled bf16 images, HMMA.
// ---------------------------------------------------------------------------
extern __shared__ char smem[];

__global__ void __launch_bounds__(256, 2)
tile_hmma_kernel() {
    const uint32_t sb = s2u(smem);
    const int t = threadIdx.x, lane = t & 31, w = t >> 5;
    const int wr = w >> 2;            // 0..1  : 64-row (n) band
    const int wc = w & 3;             // 0..3  : 32-col (m) band
    const int b = blockIdx.z, n0 = blockIdx.y * 128, m0 = blockIdx.x * 128;

    float* sx2  = (float*)(smem + SM_X2);
    float* sy2  = (float*)(smem + SM_Y2);
    float* srow = (float*)(smem + SM_ROW);
    float* scol = (float*)(smem + SM_COL);

    // Async-copy the three 16 KB tile images.
    {
        const unsigned char* asrc = g_xbf + (size_t)(b * 32 + blockIdx.y) * 16384;
        const unsigned char* hsrc = g_yhi + (size_t)(b * 32 + blockIdx.x) * 16384;
        const unsigned char* lsrc = g_ylo + (size_t)(b * 32 + blockIdx.x) * 16384;
#pragma unroll
        for (int c = 0; c < 4; c++) {
            uint32_t o = (uint32_t)(c * 4096 + t * 16);
            cp16(sb + SM_A + o, asrc + o);
            cp16(sb + SM_BHI + o, hsrc + o);
            cp16(sb + SM_BLO + o, lsrc + o);
        }
        asm volatile("cp.async.commit_group;" ::: "memory");
    }

    if (t < 128) { sx2[t] = g_x2[b * NN + n0 + t]; srow[t] = FINF; }
    else { sy2[t - 128] = g_y2[b * MM + m0 + t - 128]; scol[t - 128] = FINF; }

    // Per-lane ldmatrix base offsets (bytes, pre-swizzle).
    const int tq = lane >> 3, tr = lane & 7;
    uint32_t aOff[4], bOff[4];
#pragma unroll
    for (int mt = 0; mt < 4; mt++)
        aOff[mt] = (uint32_t)((wr * 64 + mt * 16 + (tq & 1) * 8 + tr) * 128 +
                              (tq >> 1) * 16);
    const int l16 = lane & 15;
#pragma unroll
    for (int nt = 0; nt < 4; nt++)
        bOff[nt] = (uint32_t)((wc * 32 + nt * 8 + (l16 & 7)) * 128 +
                              (l16 >> 3) * 16);

    float acc[4][4][4];
#pragma unroll
    for (int i = 0; i < 4; i++)
#pragma unroll
        for (int j = 0; j < 4; j++)
#pragma unroll
            for (int e = 0; e < 4; e++) acc[i][j][e] = 0.f;

    asm volatile("cp.async.wait_group 0;" ::: "memory");
    __syncthreads();

    // K loop: per k16 block load A once, run B_hi then B_lo phases.
#pragma unroll
    for (int kk = 0; kk < 4; kk++) {
        const uint32_t kcol = kk * 32;

        uint32_t a[4][4];
#pragma unroll
        for (int mt = 0; mt < 4; mt++) {
            uint32_t addr = sb + SM_A + SWZ(aOff[mt] + kcol);
            asm volatile("ldmatrix.sync.aligned.m8n8.x4.shared.b16 "
                         "{%0,%1,%2,%3}, [%4];"
                         : "=r"(a[mt][0]), "=r"(a[mt][1]),
                           "=r"(a[mt][2]), "=r"(a[mt][3]) : "r"(addr));
        }
#pragma unroll
        for (int ph = 0; ph < 2; ph++) {
            const uint32_t bbase = sb + (ph ? SM_BLO : SM_BHI);
            uint32_t bf[4][2];
#pragma unroll
            for (int nt = 0; nt < 4; nt++) {
                uint32_t addr = bbase + SWZ(bOff[nt] + kcol);
                asm volatile("ldmatrix.sync.aligned.m8n8.x2.shared.b16 "
                             "{%0,%1}, [%2];"
                             : "=r"(bf[nt][0]), "=r"(bf[nt][1]) : "r"(addr));
            }
#pragma unroll
            for (int mt = 0; mt < 4; mt++)
#pragma unroll
                for (int nt = 0; nt < 4; nt++)
                    mma16816(acc[mt][nt], a[mt], bf[nt]);
        }
    }

    // Epilogue: fragment (m16n8): elem e -> row l/4 + (e>>1)*8, col 2*(l%4)+(e&1)
    float x2r[8], y2c[8];
#pragma unroll
    for (int mt = 0; mt < 4; mt++)
#pragma unroll
        for (int s = 0; s < 2; s++)
            x2r[mt * 2 + s] = sx2[wr * 64 + mt * 16 + (lane >> 2) + s * 8];
#pragma unroll
    for (int nt = 0; nt < 4; nt++)
#pragma unroll
        for (int e = 0; e < 2; e++)
            y2c[nt * 2 + e] = sy2[wc * 32 + nt * 8 + 2 * (lane & 3) + e];

    float rowmin[8], colmin[8];
#pragma unroll
    for (int i = 0; i < 8; i++) { rowmin[i] = FINF; colmin[i] = FINF; }

#pragma unroll
    for (int mt = 0; mt < 4; mt++)
#pragma unroll
        for (int nt = 0; nt < 4; nt++)
#pragma unroll
            for (int e = 0; e < 4; e++) {
                const int ri = mt * 2 + (e >> 1), cj = nt * 2 + (e & 1);
                float v = -2.f * acc[mt][nt][e];
                rowmin[ri] = fminf(rowmin[ri], v + y2c[cj]);
                colmin[cj] = fminf(colmin[cj], v + x2r[ri]);
            }

    // Row mins: reduce over lanes sharing a row (xor 1,2).
#pragma unroll
    for (int off = 1; off <= 2; off <<= 1)
#pragma unroll
        for (int i = 0; i < 8; i++)
            rowmin[i] = fminf(rowmin[i], __shfl_xor_sync(~0u, rowmin[i], off));
    if ((lane & 3) == 0) {
#pragma unroll
        for (int mt = 0; mt < 4; mt++)
#pragma unroll
            for (int s = 0; s < 2; s++) {
                int row = wr * 64 + mt * 16 + (lane >> 2) + s * 8;
                float v = fmaxf(rowmin[mt * 2 + s] + x2r[mt * 2 + s], 0.f);
                atomicMin((int*)&srow[row], __float_as_int(v));
            }
    }

    // Col mins: reduce over lanes sharing a col (xor 4,8,16).
#pragma unroll
    for (int off = 4; off <= 16; off <<= 1)
#pragma unroll
        for (int i = 0; i < 8; i++)
            colmin[i] = fminf(colmin[i], __shfl_xor_sync(~0u, colmin[i], off));
    if (lane < 4) {
#pragma unroll
        for (int nt = 0; nt < 4; nt++)
#pragma unroll
            for (int e = 0; e < 2; e++) {
                int col = wc * 32 + nt * 8 + 2 * lane + e;
                float v = fmaxf(colmin[nt * 2 + e] + y2c[nt * 2 + e], 0.f);
                atomicMin((int*)&scol[col], __float_as_int(v));
            }
    }

    __syncthreads();
    if (t < 128)
        atomicMin((int*)&g_min_m[blockIdx.z * NN + n0 + t],
                  __float_as_int(srow[t]));
    else
        atomicMin((int*)&g_min_n[blockIdx.z * MM + m0 + t - 128],
                  __float_as_int(scol[t - 128]));
}

// ---------------------------------------------------------------------------
// Kernel 3: loss = sum(sqrt(mins)) / (B * 4096)
// ---------------------------------------------------------------------------
__global__ void reduce_kernel(float* __restrict__ out) {
    __shared__ float ssum[1024];
    int t = threadIdx.x;
    float s = 0.f;
    for (int i = t; i < BB * NN; i += 1024)
        s += sqrtf(g_min_m[i]) + sqrtf(g_min_n[i]);
    ssum[t] = s;
    __syncthreads();
#pragma unroll
    for (int off = 512; off > 0; off >>= 1) {
        if (t < off) ssum[t] += ssum[t + off];
        __syncthreads();
    }
    if (t == 0) out[0] = ssum[0] * (1.0f / (BB * NN));
}

// ---------------------------------------------------------------------------
extern "C" void kernel_launch(void* const* d_in, const int* in_sizes, int n_in,
                              void* d_out, int out_size) {
    const float* x = (const float*)d_in[0];   // input1 [B, N, K]
    const float* y = (const float*)d_in[1];   // input2 [B, M, K]
    float* out = (float*)d_out;

    cudaFuncSetAttribute(tile_hmma_kernel,
                         cudaFuncAttributeMaxDynamicSharedMemorySize, SMEM_SZ);

    prep_kernel<<<(2 * BB * NN * 16) / 256, 256>>>(x, y);

    dim3 grid(MM / 128, NN / 128, BB);
    tile_hmma_kernel<<<grid, 256, SMEM_SZ>>>();

    reduce_kernel<<<1, 1024>>>(out);
}